// round 17
// baseline (speedup 1.0000x reference)
#include <cuda_runtime.h>
#include <cuda_fp16.h>
#include <math.h>
#include <stdint.h>

// ---------------- problem constants ----------------
#define NTOK   8192
#define CDIM   512
#define FFDIM  2048
#define NHEAD  8
#define HD     64
#define SEQ    1024
#define NBATCH 8

// ---------------- scratch ----------------
__device__ float g_xn  [NTOK * CDIM];
__device__ float g_attn[NTOK * CDIM];
__device__ float g_yn  [NTOK * CDIM];

__device__ __half g_xnf[NTOK * CDIM];
__device__ __half g_ynf[NTOK * CDIM];
__device__ __half g_q  [NTOK * CDIM];
__device__ __half g_k  [NTOK * CDIM];
__device__ __half g_vt [NTOK * CDIM];     // V^T [b*8+h][d][kv]
__device__ __half g_o  [NTOK * CDIM];
__device__ __half g_h1 [NTOK * FFDIM];

__device__ __half g_wqkv[3 * CDIM * CDIM];  // rows 0-511 Wq^T(/8), 512-1023 Wk^T, 1024-1535 Wv^T
__device__ __half g_wot[CDIM * CDIM];
__device__ __half g_f1t[CDIM * FFDIM];
__device__ __half g_f2t[FFDIM * CDIM];

// ---------------- helpers ----------------
__device__ __forceinline__ uint32_t smem_u32(const void* p) {
    uint32_t a;
    asm("{ .reg .u64 t; cvta.to.shared.u64 t, %1; cvt.u32.u64 %0, t; }" : "=r"(a) : "l"(p));
    return a;
}
__device__ __forceinline__ void cpa16(uint32_t s, const void* g) {
    asm volatile("cp.async.cg.shared.global [%0], [%1], 16;" :: "r"(s), "l"(g) : "memory");
}
#define CP_COMMIT() asm volatile("cp.async.commit_group;" ::: "memory")

__device__ __forceinline__ void mma16816(float* c, const uint32_t* a, const uint32_t* b) {
    asm volatile("mma.sync.aligned.m16n8k16.row.col.f32.f16.f16.f32 "
        "{%0,%1,%2,%3}, {%4,%5,%6,%7}, {%8,%9}, {%0,%1,%2,%3};"
        : "+f"(c[0]), "+f"(c[1]), "+f"(c[2]), "+f"(c[3])
        : "r"(a[0]), "r"(a[1]), "r"(a[2]), "r"(a[3]), "r"(b[0]), "r"(b[1]));
}
__device__ __forceinline__ void ldm_x4(uint32_t* r, uint32_t addr) {
    asm volatile("ldmatrix.sync.aligned.m8n8.x4.shared.b16 {%0,%1,%2,%3}, [%4];"
        : "=r"(r[0]), "=r"(r[1]), "=r"(r[2]), "=r"(r[3]) : "r"(addr));
}

// ---------------- LayerNorm (fp32 out + fp16) ----------------
__global__ __launch_bounds__(128) void ln_kernel(
    const float* __restrict__ in, const float* __restrict__ gam,
    const float* __restrict__ bet, float* __restrict__ out,
    __half* __restrict__ oh)
{
    const int row = blockIdx.x;
    const int t = threadIdx.x;
    const float4* x4 = (const float4*)(in + (size_t)row * CDIM);
    float4 v = x4[t];
    float s  = v.x + v.y + v.z + v.w;
    float ss = fmaf(v.x, v.x, fmaf(v.y, v.y, fmaf(v.z, v.z, v.w * v.w)));
    #pragma unroll
    for (int o = 16; o > 0; o >>= 1) {
        s  += __shfl_xor_sync(0xffffffffu, s,  o);
        ss += __shfl_xor_sync(0xffffffffu, ss, o);
    }
    __shared__ float sh[4], shh[4];
    const int wid = t >> 5, lane = t & 31;
    if (lane == 0) { sh[wid] = s; shh[wid] = ss; }
    __syncthreads();
    float tot  = sh[0] + sh[1] + sh[2] + sh[3];
    float tot2 = shh[0] + shh[1] + shh[2] + shh[3];
    const float mean = tot * (1.0f / CDIM);
    const float var  = tot2 * (1.0f / CDIM) - mean * mean;
    const float r    = rsqrtf(var + 1e-5f);
    float4 g = ((const float4*)gam)[t];
    float4 b = ((const float4*)bet)[t];
    float o4[4];
    o4[0] = (v.x - mean) * r * g.x + b.x;
    o4[1] = (v.y - mean) * r * g.y + b.y;
    o4[2] = (v.z - mean) * r * g.z + b.z;
    o4[3] = (v.w - mean) * r * g.w + b.w;
    ((float4*)(out + (size_t)row * CDIM))[t] = make_float4(o4[0], o4[1], o4[2], o4[3]);
    size_t base = (size_t)row * CDIM + t * 4;
    __half2 p0; p0.x = __float2half_rn(o4[0]); p0.y = __float2half_rn(o4[1]);
    __half2 p1; p1.x = __float2half_rn(o4[2]); p1.y = __float2half_rn(o4[3]);
    *(__half2*)(oh + base)     = p0;
    *(__half2*)(oh + base + 2) = p1;
}

// ------------- weight transposes (fp16), bid0-offset so it can be split ---
__global__ __launch_bounds__(256) void transconv_all(
    const float* __restrict__ Wq, const float* __restrict__ Wk,
    const float* __restrict__ Wv, const float* __restrict__ Wo,
    const float* __restrict__ F1, const float* __restrict__ F2, int bid0)
{
    const int bid = blockIdx.x + bid0;
    const float* W; __half* Th;
    int K, N, nb, idx, noff = 0; float scale = 1.0f;
    if (bid < 768) {                          // QKV -> fused buffer
        int which = bid >> 8; idx = bid & 255; K = 512; N = 512; nb = 16;
        Th = g_wqkv; noff = which * 512;
        if (which == 0)      { W = Wq; scale = 0.125f; }
        else if (which == 1) { W = Wk; }
        else                 { W = Wv; }
    } else if (bid < 1024) {
        idx = bid - 768; W = Wo; Th = g_wot; K = 512; N = 512; nb = 16;
    } else if (bid < 2048) {
        idx = bid - 1024; W = F1; Th = g_f1t; K = 512; N = 2048; nb = 64;
    } else {
        idx = bid - 2048; W = F2; Th = g_f2t; K = 2048; N = 512; nb = 16;
    }
    const int n0 = (idx % nb) * 32, k0 = (idx / nb) * 32;
    __shared__ float t[32][33];
    const int tx = threadIdx.x & 31, ty = threadIdx.x >> 5;
    #pragma unroll
    for (int i = 0; i < 4; i++)
        t[ty + i * 8][tx] = W[(size_t)(k0 + ty + i * 8) * N + n0 + tx];
    __syncthreads();
    #pragma unroll
    for (int i = 0; i < 4; i++) {
        int r = ty + i * 8;
        Th[(size_t)(noff + n0 + r) * K + k0 + tx] = __float2half_rn(t[tx][r] * scale);
    }
}

// -------- mma.sync fp16 GEMM: KC=64, 3-stage single-sync pipeline ---------
#define BM 128
#define BN 128
#define KC 64
#define ROWB 144
#define MAT_BYTES (128 * ROWB)               // 18432
#define A_OFF 0
#define B_OFF MAT_BYTES
#define STAGE_BYTES (2 * MAT_BYTES)          // 36864
#define GT_SMEM (3 * STAGE_BYTES)            // 110592

// OM: 0 = fp32 Cf; 2 = fp16 Ch; 4 = fused QKV routing (col 0..1535)
template <bool BIAS, bool RES, bool RELU, int OM>
__global__ __launch_bounds__(256, 2) void gemm_mma(
    const __half* __restrict__ A, const __half* __restrict__ B,
    const float* __restrict__ bias, const float* __restrict__ res,
    float* __restrict__ Cf, __half* __restrict__ Ch, int M, int N, int K)
{
    extern __shared__ char sm[];
    const uint32_t sbase = smem_u32(sm);
    const int tid  = threadIdx.x;
    const int lane = tid & 31;
    const int warp = tid >> 5;
    const int wm0  = (warp & 3) * 32;
    const int wn0  = (warp >> 2) * 64;
    const int g    = lane >> 2;
    const int tig  = lane & 3;
    const int t8   = lane >> 3;
    const int r8   = lane & 7;
    const int bm0  = blockIdx.y * BM;
    const int bn0  = blockIdx.x * BN;

    float acc[2][8][4];
    #pragma unroll
    for (int i = 0; i < 2; i++)
        #pragma unroll
        for (int j = 0; j < 8; j++)
            #pragma unroll
            for (int e = 0; e < 4; e++) acc[i][j][e] = 0.0f;

    auto load_stage = [&](int kt, int buf) {
        const uint32_t st = sbase + buf * STAGE_BYTES;
        #pragma unroll
        for (int i = 0; i < 8; i++) {
            int idx = tid + i * 256;              // 0..2047
            int mat = idx >> 10;                  // 0..1
            int rix = idx & 1023;
            int r   = rix >> 3;                   // 0..127
            int cb  = (rix & 7) * 16;             // 0..112
            const __half* gs = mat ? B : A;
            int grow = mat ? (bn0 + r) : (bm0 + r);
            const char* src = (const char*)(gs + (size_t)grow * K + kt) + cb;
            cpa16(st + mat * MAT_BYTES + r * ROWB + cb, src);
        }
        CP_COMMIT();
    };

    const int S = K / KC;
    load_stage(0, 0);
    load_stage(KC, 1);

    int buf = 0;
    for (int s = 0; s < S; s++) {
        if (s + 1 < S) asm volatile("cp.async.wait_group 1;" ::: "memory");
        else           asm volatile("cp.async.wait_group 0;" ::: "memory");
        __syncthreads();
        if (s + 2 < S) {
            int nb = buf + 2; if (nb >= 3) nb -= 3;
            load_stage((s + 2) * KC, nb);
        }

        const uint32_t sb32 = sbase + buf * STAGE_BYTES;
        #pragma unroll
        for (int kk = 0; kk < 4; kk++) {
            const int kbyte = kk * 32;
            uint32_t aF[2][4];
            #pragma unroll
            for (int am = 0; am < 2; am++) {
                uint32_t arow = wm0 + am * 16 + (t8 & 1) * 8 + r8;
                uint32_t acol = kbyte + (t8 >> 1) * 16;
                ldm_x4(aF[am], sb32 + A_OFF + arow * ROWB + acol);
            }
            #pragma unroll
            for (int bn2 = 0; bn2 < 4; bn2++) {
                uint32_t brow = wn0 + (2 * bn2 + (t8 >> 1)) * 8 + r8;
                uint32_t bcol = kbyte + (t8 & 1) * 16;
                uint32_t b4[4];
                ldm_x4(b4, sb32 + B_OFF + brow * ROWB + bcol);
                #pragma unroll
                for (int half = 0; half < 2; half++) {
                    const int bn = 2 * bn2 + half;
                    const uint32_t* b = b4 + 2 * half;
                    mma16816(acc[0][bn], aF[0], b);
                    mma16816(acc[1][bn], aF[1], b);
                }
            }
        }
        if (++buf == 3) buf = 0;
    }

    // epilogue
    #pragma unroll
    for (int am = 0; am < 2; am++) {
        #pragma unroll
        for (int bn = 0; bn < 8; bn++) {
            const int row = bm0 + wm0 + am * 16 + g;
            const int col = bn0 + wn0 + bn * 8 + 2 * tig;
            float* c = acc[am][bn];
            #pragma unroll
            for (int h = 0; h < 2; h++) {
                const int r = row + h * 8;
                float v0 = c[h * 2 + 0];
                float v1 = c[h * 2 + 1];
                if (BIAS) { v0 += bias[col]; v1 += bias[col + 1]; }
                if (RES) {
                    float2 rr = *(const float2*)&res[(size_t)r * N + col];
                    v0 += rr.x; v1 += rr.y;
                }
                if (RELU) { v0 = fmaxf(v0, 0.f); v1 = fmaxf(v1, 0.f); }
                if (OM == 4) {
                    if (col < 1024) {
                        __half* dst = (col < 512) ? g_q : g_k;
                        int cc = col & 511;
                        __half2 hp; hp.x = __float2half_rn(v0); hp.y = __float2half_rn(v1);
                        *(__half2*)(dst + (size_t)r * CDIM + cc) = hp;
                    } else {
                        int cc = col - 1024;
                        int head = cc >> 6, d = cc & 63;
                        int bb = r >> 10, kv = r & 1023;
                        size_t tb = ((size_t)(bb * 8 + head) * 64 + d) * 1024 + kv;
                        g_vt[tb]        = __float2half_rn(v0);
                        g_vt[tb + 1024] = __float2half_rn(v1);
                    }
                } else if (OM == 2) {
                    __half2 hp; hp.x = __float2half_rn(v0); hp.y = __float2half_rn(v1);
                    *(__half2*)(Ch + (size_t)r * N + col) = hp;
                } else {
                    *(float2*)&Cf[(size_t)r * N + col] = make_float2(v0, v1);
                }
            }
        }
    }
}

// -------- mma attention: 512 threads; k-split PV with smem reduction ------
#define PSTR    1040
#define S_BYTES (32 * PSTR * 4)              // 133120
#define Q_OFF   S_BYTES
#define QROW    144
#define Q_BYTES (32 * QROW)                  // 4608
#define KV_OFF  (Q_OFF + Q_BYTES)            // 137728
#define KROW 144
#define KMAT (128 * KROW)                    // 18432
#define VROW 272
#define VMAT (64 * VROW)                     // 17408
#define ATTN_SMEM (KV_OFF + 3 * KMAT)        // 193024

__global__ __launch_bounds__(512, 1) void attn_mma(float* __restrict__ probs)
{
    extern __shared__ char sm[];
    float* S = (float*)sm;
    uint32_t* Su = (uint32_t*)sm;
    const uint32_t sb = smem_u32(sm);
    const int tid = threadIdx.x, lane = tid & 31, warp = tid >> 5;
    const int wq = warp >> 3;            // QK: 0..1 q half
    const int wv = warp & 7;             // QK: 0..7 kv tile
    const int wk = warp & 3;             // PV: k quarter
    const int wd = warp >> 2;            // PV: d group of 16 (0..3)
    const int g = lane >> 2, tig = lane & 3;
    const int t8 = lane >> 3, r8 = lane & 7;
    const int qb = blockIdx.x, hd = blockIdx.y, b = blockIdx.z;
    const int q0 = qb * 32;
    const size_t tokbase = (size_t)b * SEQ;

    if (tid < 256) {
        int r = tid >> 3, v = (tid & 7) * 16;
        const char* sp = (const char*)(g_q + (tokbase + q0 + r) * CDIM + hd * HD) + v;
        *(uint4*)(sm + Q_OFF + r * QROW + v) = *(const uint4*)sp;
    }

    auto load_k = [&](int kv0, int buf) {
        const uint32_t st = sb + KV_OFF + buf * KMAT;
        #pragma unroll
        for (int i = 0; i < 2; i++) {
            int idx = tid + i * 512;
            int r = idx >> 3, v = (idx & 7) * 16;
            const char* sp = (const char*)(g_k + (tokbase + kv0 + r) * CDIM + hd * HD) + v;
            cpa16(st + r * KROW + v, sp);
        }
        CP_COMMIT();
    };
    auto load_v = [&](int kv0, int buf) {
        const uint32_t st = sb + KV_OFF + buf * VMAT;
        #pragma unroll
        for (int i = 0; i < 2; i++) {
            int idx = tid + i * 512;
            int r = idx >> 4, v = (idx & 15) * 16;
            const char* sp = (const char*)(g_vt + ((size_t)(b * 8 + hd) * 64 + r) * SEQ + kv0) + v;
            cpa16(st + r * VROW + v, sp);
        }
        CP_COMMIT();
    };

    load_k(0, 0);
    load_k(128, 1);

    const uint32_t sbQ = sb + Q_OFF;

    // ---- scores S = Q @ K^T (Wq pre-scaled by 1/8) ----
    int kbuf = 0;
    for (int ch = 0; ch < 8; ch++) {
        if (ch < 7) asm volatile("cp.async.wait_group 1;" ::: "memory");
        else        asm volatile("cp.async.wait_group 0;" ::: "memory");
        __syncthreads();
        if (ch + 2 < 8) {
            int nb = kbuf + 2; if (nb >= 3) nb -= 3;
            load_k((ch + 2) * 128, nb);
        }
        const uint32_t kb32 = sb + KV_OFF + kbuf * KMAT;
        float c[2][4];
        #pragma unroll
        for (int nt = 0; nt < 2; nt++)
            #pragma unroll
            for (int e = 0; e < 4; e++) c[nt][e] = 0.0f;

        #pragma unroll
        for (int kk = 0; kk < 4; kk++) {
            const int kbyte = kk * 32;
            uint32_t aF[4];
            uint32_t arow = wq * 16 + (t8 & 1) * 8 + r8;
            uint32_t acol = kbyte + (t8 >> 1) * 16;
            ldm_x4(aF, sbQ + arow * QROW + acol);
            uint32_t krow = wv * 16 + (t8 >> 1) * 8 + r8;
            uint32_t kf[4];
            ldm_x4(kf, kb32 + krow * KROW + kbyte + (t8 & 1) * 16);
            mma16816(c[0], aF, kf);
            mma16816(c[1], aF, kf + 2);
        }
        #pragma unroll
        for (int nt = 0; nt < 2; nt++) {
            int row = wq * 16 + g;
            int col = ch * 128 + wv * 16 + nt * 8 + 2 * tig;
            *(float2*)&S[row * PSTR + col] = make_float2(c[nt][0], c[nt][1]);
            *(float2*)&S[(row + 8) * PSTR + col] = make_float2(c[nt][2], c[nt][3]);
        }
        if (++kbuf == 3) kbuf = 0;
    }

    __syncthreads();
    load_v(0, 0);
    load_v(128, 1);

    // ---- softmax (2 rows/warp); probs out; packed fp16 P in S ------------
    #pragma unroll
    for (int rr = 0; rr < 2; rr++) {
        int row = warp * 2 + rr;
        float4 vals[8];
        float mx = -1e30f;
        #pragma unroll
        for (int v = 0; v < 8; v++) {
            vals[v] = *(float4*)&S[row * PSTR + (v * 32 + lane) * 4];
            mx = fmaxf(mx, fmaxf(fmaxf(vals[v].x, vals[v].y), fmaxf(vals[v].z, vals[v].w)));
        }
        #pragma unroll
        for (int o = 16; o > 0; o >>= 1) mx = fmaxf(mx, __shfl_xor_sync(0xffffffffu, mx, o));
        float sum = 0.f;
        #pragma unroll
        for (int v = 0; v < 8; v++) {
            vals[v].x = __expf(vals[v].x - mx);
            vals[v].y = __expf(vals[v].y - mx);
            vals[v].z = __expf(vals[v].z - mx);
            vals[v].w = __expf(vals[v].w - mx);
            sum += vals[v].x + vals[v].y + vals[v].z + vals[v].w;
        }
        #pragma unroll
        for (int o = 16; o > 0; o >>= 1) sum += __shfl_xor_sync(0xffffffffu, sum, o);
        float inv = 1.0f / sum;
        size_t pbase = ((tokbase + q0 + row) * NHEAD + hd) * SEQ;
        #pragma unroll
        for (int v = 0; v < 8; v++) {
            int cc = (v * 32 + lane) * 4;
            float p[4] = {vals[v].x * inv, vals[v].y * inv, vals[v].z * inv, vals[v].w * inv};
            *(float4*)&probs[pbase + cc] = make_float4(p[0], p[1], p[2], p[3]);
            __half2 w0; w0.x = __float2half_rn(p[0]); w0.y = __float2half_rn(p[1]);
            __half2 w1; w1.x = __float2half_rn(p[2]); w1.y = __float2half_rn(p[3]);
            int cg = cc >> 4;
            int j0 = (cc & 15) >> 1;
            int base = row * PSTR + cg * 8;
            Su[base + 2 * (j0 & 3) + (j0 >> 2)]             = *(uint32_t*)&w0;
            Su[base + 2 * ((j0 + 1) & 3) + ((j0 + 1) >> 2)] = *(uint32_t*)&w1;
        }
    }
    __syncthreads();

    // ---- O = P @ V, k-split: warp (wk, wd) does 32q x 16d over its 32-kv
    //      quarter of each chunk; partials reduced via smem afterwards ----
    float o[2][2][4];
    #pragma unroll
    for (int am = 0; am < 2; am++)
        #pragma unroll
        for (int nd = 0; nd < 2; nd++)
            #pragma unroll
            for (int e = 0; e < 4; e++) o[am][nd][e] = 0.0f;

    int vbuf = 0;
    for (int ch = 0; ch < 8; ch++) {
        if (ch < 7) asm volatile("cp.async.wait_group 1;" ::: "memory");
        else        asm volatile("cp.async.wait_group 0;" ::: "memory");
        __syncthreads();
        if (ch + 2 < 8) {
            int nb = vbuf + 2; if (nb >= 3) nb -= 3;
            load_v((ch + 2) * 128, nb);
        }
        const uint32_t vb32 = sb + KV_OFF + vbuf * VMAT;
        #pragma unroll
        for (int kki = 0; kki < 2; kki++) {
            const int kloc  = wk * 32 + kki * 16;         // 0..127
            const int kbyte = kloc * 2;
            const int cg    = ch * 8 + (kloc >> 4);
            uint32_t vf[4];
            ldm_x4(vf, vb32 + (wd * 16 + (t8 >> 1) * 8 + r8) * VROW
                         + kbyte + (t8 & 1) * 16);
            #pragma unroll
            for (int am = 0; am < 2; am++) {
                int r = am * 16 + g;
                uint2 Ua = *(const uint2*)&Su[r * PSTR + cg * 8 + 2 * tig];
                uint2 Ub = *(const uint2*)&Su[(r + 8) * PSTR + cg * 8 + 2 * tig];
                uint32_t a[4] = {Ua.x, Ub.x, Ua.y, Ub.y};
                mma16816(o[am][0], a, vf);
                mma16816(o[am][1], a, vf + 2);
            }
        }
        if (++vbuf == 3) vbuf = 0;
    }

    // ---- reduce partials over wk (4) via smem (reuses S region) ----------
    __syncthreads();                     // all Su reads done before overwrite
    float* Ored = S;                     // [4][32][64] = 32 KB
    #pragma unroll
    for (int am = 0; am < 2; am++)
        #pragma unroll
        for (int nd = 0; nd < 2; nd++)
            #pragma unroll
            for (int h = 0; h < 2; h++) {
                int q = am * 16 + g + h * 8;
                int d = wd * 16 + nd * 8 + 2 * tig;
                *(float2*)&Ored[(wk * 32 + q) * 64 + d] =
                    make_float2(o[am][nd][h * 2 + 0], o[am][nd][h * 2 + 1]);
            }
    __syncthreads();
    {
        int idx = tid * 4;               // 512 threads x 4 = 2048 = 32q x 64d
        int q = idx >> 6, d = idx & 63;
        float4 s0 = *(const float4*)&Ored[(0 * 32 + q) * 64 + d];
        float4 s1 = *(const float4*)&Ored[(1 * 32 + q) * 64 + d];
        float4 s2 = *(const float4*)&Ored[(2 * 32 + q) * 64 + d];
        float4 s3 = *(const float4*)&Ored[(3 * 32 + q) * 64 + d];
        float r0 = s0.x + s1.x + s2.x + s3.x;
        float r1 = s0.y + s1.y + s2.y + s3.y;
        float r2 = s0.z + s1.z + s2.z + s3.z;
        float r3 = s0.w + s1.w + s2.w + s3.w;
        size_t off = (tokbase + q0 + q) * CDIM + hd * HD + d;
        __half2 h0; h0.x = __float2half_rn(r0); h0.y = __float2half_rn(r1);
        __half2 h1; h1.x = __float2half_rn(r2); h1.y = __float2half_rn(r3);
        *(__half2*)(g_o + off)     = h0;
        *(__half2*)(g_o + off + 2) = h1;
    }
}

// ---------------- launcher ----------------
extern "C" void kernel_launch(void* const* d_in, const int* in_sizes, int n_in,
                              void* d_out, int out_size)
{
    const float* x     = (const float*)d_in[0];
    const float* Wq    = (const float*)d_in[1];
    const float* Wk    = (const float*)d_in[2];
    const float* Wv    = (const float*)d_in[3];
    const float* Wo    = (const float*)d_in[4];
    const float* ln1_g = (const float*)d_in[5];
    const float* ln1_b = (const float*)d_in[6];
    const float* fc1_w = (const float*)d_in[7];
    const float* fc1_b = (const float*)d_in[8];
    const float* fc2_w = (const float*)d_in[9];
    const float* fc2_b = (const float*)d_in[10];
    const float* ln2_g = (const float*)d_in[11];
    const float* ln2_b = (const float*)d_in[12];

    float* out   = (float*)d_out;
    float* probs = out + (size_t)NTOK * CDIM;

    float *p_xn, *p_attn, *p_yn;
    __half *p_xnf, *p_ynf, *p_h1;
    __half *p_wqkv, *p_wot, *p_f1t, *p_f2t, *p_o;
    cudaGetSymbolAddress((void**)&p_xn,   g_xn);
    cudaGetSymbolAddress((void**)&p_attn, g_attn);
    cudaGetSymbolAddress((void**)&p_yn,   g_yn);
    cudaGetSymbolAddress((void**)&p_xnf,  g_xnf);
    cudaGetSymbolAddress((void**)&p_ynf,  g_ynf);
    cudaGetSymbolAddress((void**)&p_h1,   g_h1);
    cudaGetSymbolAddress((void**)&p_o,    g_o);
    cudaGetSymbolAddress((void**)&p_wqkv, g_wqkv);
    cudaGetSymbolAddress((void**)&p_wot,  g_wot);
    cudaGetSymbolAddress((void**)&p_f1t,  g_f1t);
    cudaGetSymbolAddress((void**)&p_f2t,  g_f2t);

    cudaFuncSetAttribute(attn_mma,
                         cudaFuncAttributeMaxDynamicSharedMemorySize, ATTN_SMEM);
    cudaFuncSetAttribute(gemm_mma<false, false, false, 4>,
                         cudaFuncAttributeMaxDynamicSharedMemorySize, GT_SMEM);
    cudaFuncSetAttribute(gemm_mma<false, true, false, 0>,
                         cudaFuncAttributeMaxDynamicSharedMemorySize, GT_SMEM);
    cudaFuncSetAttribute(gemm_mma<true, false, true, 2>,
                         cudaFuncAttributeMaxDynamicSharedMemorySize, GT_SMEM);
    cudaFuncSetAttribute(gemm_mma<true, true, false, 0>,
                         cudaFuncAttributeMaxDynamicSharedMemorySize, GT_SMEM);

    // launch 0: LN1
    ln_kernel<<<NTOK, 128>>>(x, ln1_g, ln1_b, p_xn, p_xnf);

    // launches 1-3: weight transposes
    transconv_all<<<768,  256>>>(Wq, Wk, Wv, Wo, fc1_w, fc2_w, 0);     // QKV
    transconv_all<<<256,  256>>>(Wq, Wk, Wv, Wo, fc1_w, fc2_w, 768);   // Wo
    transconv_all<<<2048, 256>>>(Wq, Wk, Wv, Wo, fc1_w, fc2_w, 1024);  // F1,F2

    // launch 4: fused QKV projection (routed epilogue)
    dim3 gqkv(3 * CDIM / BN, NTOK / BM);      // (12, 64)
    gemm_mma<false, false, false, 4><<<gqkv, 256, GT_SMEM>>>(
        p_xnf, p_wqkv, nullptr, nullptr, nullptr, nullptr, NTOK, 3 * CDIM, CDIM);

    // launch 5: attention
    attn_mma<<<dim3(32, NHEAD, NBATCH), 512, ATTN_SMEM>>>(probs);

    // launch 6: attn_out = O @ Wo + xn
    dim3 g512(CDIM / BN, NTOK / BM);          // (4, 64)
    gemm_mma<false, true, false, 0><<<g512, 256, GT_SMEM>>>(
        p_o, p_wot, nullptr, p_xn, p_attn, nullptr, NTOK, CDIM, CDIM);

    // launch 7: LN2
    ln_kernel<<<NTOK, 128>>>(p_attn, ln2_g, ln2_b, p_yn, p_ynf);

    // launch 8: h1 = relu(yn @ fc1 + b1) -> fp16
    dim3 gff(FFDIM / BN, NTOK / BM);          // (16, 64)
    gemm_mma<true, false, true, 2><<<gff, 256, GT_SMEM>>>(
        p_ynf, p_f1t, fc1_b, nullptr, nullptr, p_h1, NTOK, FFDIM, CDIM);

    // launch 9: out = h1 @ fc2 + b2 + yn
    gemm_mma<true, true, false, 0><<<g512, 256, GT_SMEM>>>(
        p_h1, p_f2t, fc2_b, p_yn, out, nullptr, NTOK, CDIM, FFDIM);
}